// round 5
// baseline (speedup 1.0000x reference)
#include <cuda_runtime.h>

// out[i,:] = 40320 * sum_j ( relu(x @ W1 + b1) @ W2 + b2 )[j,:]
// N=9, D=512, H=32, C=4. Single block, 288 threads = 9 rows x 32 hidden units.

#define N_ROWS 9
#define D_DIM  512
#define H_DIM  32
#define C_DIM  4

__global__ __launch_bounds__(N_ROWS * H_DIM)
void symnet_kernel(const float* __restrict__ x,
                   const float* __restrict__ W1,
                   const float* __restrict__ b1,
                   const float* __restrict__ W2,
                   const float* __restrict__ b2,
                   float* __restrict__ out) {
    __shared__ float s[H_DIM];

    const int t = threadIdx.x;
    if (t < H_DIM) s[t] = 0.0f;
    __syncthreads();

    const int row = t >> 5;       // 0..8 (one warp per row)
    const int h   = t & 31;       // 0..31 hidden unit

    const float* __restrict__ xr = x + row * D_DIM;

    float acc = b1[h];
    #pragma unroll 8
    for (int k = 0; k < D_DIM; ++k) {
        // W1 row k, column h: consecutive threads -> consecutive addresses (coalesced)
        acc = fmaf(xr[k], W1[k * H_DIM + h], acc);
    }
    acc = fmaxf(acc, 0.0f);

    // Sum hidden activations over the 9 rows (9 atomic adds per h — trivial)
    atomicAdd(&s[h], acc);
    __syncthreads();

    // 36 threads write the broadcast output: out[i,c] = 40320 * (s @ W2 + 9*b2)[c]
    if (t < N_ROWS * C_DIM) {
        const int c = t & 3;
        float tot = 9.0f * b2[c];
        #pragma unroll
        for (int hh = 0; hh < H_DIM; ++hh)
            tot = fmaf(s[hh], W2[hh * C_DIM + c], tot);
        out[t] = 40320.0f * tot;
    }
}

extern "C" void kernel_launch(void* const* d_in, const int* in_sizes, int n_in,
                              void* d_out, int out_size) {
    // metadata order: x, W1, b1, W2, b2, perms
    const float* x  = (const float*)d_in[0];
    const float* W1 = (const float*)d_in[1];
    const float* b1 = (const float*)d_in[2];
    const float* W2 = (const float*)d_in[3];
    const float* b2 = (const float*)d_in[4];
    // perms (d_in[5]) unused: each row appears (N-1)! times at each position.
    float* out = (float*)d_out;

    symnet_kernel<<<1, N_ROWS * H_DIM>>>(x, W1, b1, W2, b2, out);
}

// round 6
// speedup vs baseline: 2.1107x; 2.1107x over previous
#include <cuda_runtime.h>

// out[i,:] = 40320 * ( sum_j relu(x @ W1 + b1)[j,:] @ W2 + 9*b2 ), broadcast to all 9 rows.
// N=9, D=512, H=32, C=4.
//
// Strategy: 9 blocks (one per row) x 256 threads (32 h x 8 k-chunks of 64).
// Cross-block reduction via device-scope atomics into g_s[32]; the last block
// to arrive finalizes the W2 epilogue and RESETS the scratch (atomicExch),
// so every graph replay starts from a clean state. No extra kernels, no
// allocations.

#define D_DIM  512
#define H_DIM  32
#define C_DIM  4
#define N_ROWS 9
#define KC     8          // k-chunks per row
#define KLEN   (D_DIM / KC)

__device__ float        g_s[H_DIM];   // zero-initialized at load; reset each call
__device__ unsigned int g_count;      // arrival counter; reset each call

__global__ __launch_bounds__(H_DIM * KC)
void symnet_fused(const float* __restrict__ x,
                  const float* __restrict__ W1,
                  const float* __restrict__ b1,
                  const float* __restrict__ W2,
                  const float* __restrict__ b2,
                  float* __restrict__ out) {
    const int r  = blockIdx.x;          // row 0..8
    const int t  = threadIdx.x;         // 0..255
    const int h  = t & 31;              // hidden unit (lane)
    const int kc = t >> 5;              // k-chunk (warp)

    const float* __restrict__ xr = x + r * D_DIM;

    // Partial dot over this thread's 64-element k-chunk.
    // W1[k*32+h]: consecutive lanes -> consecutive addresses (coalesced 128B).
    // xr[k]: same address across the warp (broadcast).
    float acc = 0.0f;
    const int k0 = kc * KLEN;
    #pragma unroll 8
    for (int i = 0; i < KLEN; ++i) {
        const int k = k0 + i;
        acc = fmaf(xr[k], W1[k * H_DIM + h], acc);
    }

    __shared__ float sh[KC][H_DIM + 1];
    sh[kc][h] = acc;
    __syncthreads();

    // Warp 0 finishes this row: z[h] = b1[h] + sum_kc, relu, atomic-accumulate.
    if (t < H_DIM) {
        float z = b1[t];
        #pragma unroll
        for (int j = 0; j < KC; ++j) z += sh[j][t];
        z = fmaxf(z, 0.0f);

        atomicAdd(&g_s[t], z);
        __threadfence();

        unsigned old = 0;
        if (t == 0) old = atomicAdd(&g_count, 1u);
        old = __shfl_sync(0xffffffffu, old, 0);

        if (old == N_ROWS - 1) {
            // Last block: consume + reset scratch in one op.
            const float sv = atomicExch(&g_s[t], 0.0f);   // = sum over rows of relu-hidden

            float tot[C_DIM];
            #pragma unroll
            for (int c = 0; c < C_DIM; ++c) {
                float v = sv * W2[t * C_DIM + c];
                #pragma unroll
                for (int off = 16; off; off >>= 1)
                    v += __shfl_xor_sync(0xffffffffu, v, off);   // all lanes get the sum
                tot[c] = 40320.0f * (v + 9.0f * b2[c]);
            }

            // 36 outputs: out[i*4+c] = tot[c]. Lanes 0..31 cover out[0..31],
            // lanes 0..3 also cover out[32..35].
            out[t] = tot[t & 3];
            if (t < C_DIM) out[H_DIM + t] = tot[t];

            if (t == 0) atomicExch(&g_count, 0u);          // reset for next replay
        }
    }
}

extern "C" void kernel_launch(void* const* d_in, const int* in_sizes, int n_in,
                              void* d_out, int out_size) {
    // metadata order: x, W1, b1, W2, b2, perms
    const float* x  = (const float*)d_in[0];
    const float* W1 = (const float*)d_in[1];
    const float* b1 = (const float*)d_in[2];
    const float* W2 = (const float*)d_in[3];
    const float* b2 = (const float*)d_in[4];
    // perms unused: each source row appears (N-1)! = 40320 times at every
    // output position, so the permutation sum collapses analytically.
    float* out = (float*)d_out;

    symnet_fused<<<N_ROWS, H_DIM * KC>>>(x, W1, b1, W2, b2, out);
}

// round 12
// speedup vs baseline: 2.7488x; 1.3023x over previous
#include <cuda_runtime.h>

// out[i,:] = 40320 * ( sum_j relu(x @ W1 + b1)[j,:] @ W2 + 9*b2 ), broadcast to 9 rows.
// N=9, D=512, H=32, C=4.
//
// 9 blocks (one per row) x 512 threads. Thread t = kc*8 + hq:
//   kc in [0,64): 8-wide k-chunk;  hq in [0,8): quad of hidden units (h = 4*hq..4*hq+3).
// Each thread: 8 float4 W1 loads + 2 float4 x loads (10 independent loads -> one
// exposed latency round), 32 FMAs into 4 accumulators.
// Reduce kc: 2 xor-shuffles (within-warp) -> shared [16][8] float4 -> warp 0 sums.
// Cross-block: device atomics; last-arriving block runs the W2 epilogue and resets
// the scratch with atomicExch so every graph replay starts clean.

#define D_DIM  512
#define H_DIM  32
#define C_DIM  4
#define N_ROWS 9
#define NT     512
#define KLEN   8          // k elements per thread
#define NWARP  16

__device__ float        g_s[H_DIM];   // zero at load; reset every call
__device__ unsigned int g_count;      // reset every call

__global__ __launch_bounds__(NT)
void symnet_fused(const float* __restrict__ x,
                  const float* __restrict__ W1,
                  const float* __restrict__ b1,
                  const float* __restrict__ W2,
                  const float* __restrict__ b2,
                  float* __restrict__ out) {
    const int r    = blockIdx.x;        // row 0..8
    const int t    = threadIdx.x;       // 0..511
    const int hq   = t & 7;             // h quad: h = 4*hq + comp
    const int kc   = t >> 3;            // 0..63
    const int w    = t >> 5;            // warp 0..15
    const int lane = t & 31;

    const float4* __restrict__ x4  = (const float4*)(x + r * D_DIM) + kc * (KLEN / 4);
    const float4* __restrict__ W14 = (const float4*)W1;   // W1[k][h]: quad (k*8+hq)

    // ---- batched loads: 2 x-quads + 8 W1-quads, all independent ----
    float4 xa = x4[0];
    float4 xb = x4[1];
    float4 wq[KLEN];
    const int k0 = kc * KLEN;
    #pragma unroll
    for (int i = 0; i < KLEN; ++i)
        wq[i] = W14[(k0 + i) * 8 + hq];

    float4 acc = make_float4(0.f, 0.f, 0.f, 0.f);
    const float xs[KLEN] = {xa.x, xa.y, xa.z, xa.w, xb.x, xb.y, xb.z, xb.w};
    #pragma unroll
    for (int i = 0; i < KLEN; ++i) {
        acc.x = fmaf(xs[i], wq[i].x, acc.x);
        acc.y = fmaf(xs[i], wq[i].y, acc.y);
        acc.z = fmaf(xs[i], wq[i].z, acc.z);
        acc.w = fmaf(xs[i], wq[i].w, acc.w);
    }

    // ---- combine the 4 kc-chunks inside each warp (lane = kcl*8 + hq) ----
    #pragma unroll
    for (int off = 8; off <= 16; off <<= 1) {
        acc.x += __shfl_xor_sync(0xffffffffu, acc.x, off);
        acc.y += __shfl_xor_sync(0xffffffffu, acc.y, off);
        acc.z += __shfl_xor_sync(0xffffffffu, acc.z, off);
        acc.w += __shfl_xor_sync(0xffffffffu, acc.w, off);
    }

    __shared__ float4 sh[NWARP][8];     // per-warp partial hidden quads
    __shared__ float  sv_sh[H_DIM];     // redistributed row-sums for epilogue
    if (lane < 8) sh[w][lane] = acc;
    __syncthreads();

    // ---- warp 0 finishes this row ----
    if (t < H_DIM) {
        const int h = t;
        const float* shf = (const float*)sh;      // [16][32] floats: shf[warp*32 + h]
        float z = b1[h];
        #pragma unroll
        for (int j = 0; j < NWARP; ++j)
            z += shf[j * H_DIM + h];
        z = fmaxf(z, 0.0f);

        atomicAdd(&g_s[h], z);
        __threadfence();

        unsigned old = 0;
        if (t == 0) old = atomicAdd(&g_count, 1u);
        old = __shfl_sync(0xffffffffu, old, 0);

        if (old == N_ROWS - 1) {
            // Last block: consume + reset scratch in one op.
            const float sv = atomicExch(&g_s[h], 0.0f);  // sum over rows of relu-hidden
            sv_sh[h] = sv;
            __syncwarp();

            // lane l: c = l&3, h0 = l>>2 in [0,8); covers hh = h0 + 8j, j<4
            // (32 lanes x 4 = 128 products = all (h,c) pairs exactly once).
            const int c  = lane & 3;
            const int h0 = lane >> 2;
            float v = 0.0f;
            #pragma unroll
            for (int j = 0; j < 4; ++j) {
                const int hh = h0 + 8 * j;                 // < 32
                v = fmaf(sv_sh[hh], W2[hh * C_DIM + c], v);
            }
            // Sum across the 8 lanes sharing c (bits 2..4 of lane = h0):
            v += __shfl_xor_sync(0xffffffffu, v, 4);
            v += __shfl_xor_sync(0xffffffffu, v, 8);
            v += __shfl_xor_sync(0xffffffffu, v, 16);

            const float tot = 40320.0f * (v + 9.0f * b2[c]);

            // 36 outputs: out[i*4+c]. Lane l covers out[l]; lanes 0..3 also out[32..35].
            out[lane] = tot;
            if (lane < C_DIM) out[H_DIM + lane] = tot;

            if (t == 0) atomicExch(&g_count, 0u);    // reset for next replay
        }
    }
}

extern "C" void kernel_launch(void* const* d_in, const int* in_sizes, int n_in,
                              void* d_out, int out_size) {
    // metadata order: x, W1, b1, W2, b2, perms
    const float* x  = (const float*)d_in[0];
    const float* W1 = (const float*)d_in[1];
    const float* b1 = (const float*)d_in[2];
    const float* W2 = (const float*)d_in[3];
    const float* b2 = (const float*)d_in[4];
    // perms unused: each source row appears (N-1)! = 40320 times at every
    // output position, so the permutation sum collapses analytically.
    float* out = (float*)d_out;

    symnet_fused<<<N_ROWS, NT>>>(x, W1, b1, W2, b2, out);
}